// round 13
// baseline (speedup 1.0000x reference)
#include <cuda_runtime.h>
#include <cuda_fp16.h>
#include <math.h>
#include <stdint.h>

#define BATCH 2
#define SEQ   2048
#define DM    2048
#define NH    16
#define DKH   128
#define MTOT  (BATCH*SEQ)   // 4096
#define BH    (BATCH*NH)    // 32

// ---- scratch (device globals) ----
__device__ float g_q[MTOT*DM];
__device__ float g_k[MTOT*DM];
__device__ float g_v[MTOT*DM];
__device__ __half g_x16[MTOT*DM];
__device__ __half g_w16[4][DM*DM];
__device__ __half g_c16[MTOT*DM];
// attention operands
__device__ __half g_qh[BH*SEQ*DKH];
__device__ __half g_ql[BH*SEQ*DKH];
__device__ __half g_kh[BH*SEQ*DKH];
__device__ __half g_vth[BH*DKH*SEQ];

// ============================================================
// helpers
// ============================================================
__device__ __forceinline__ uint32_t smem_u32(const void* p) {
    uint32_t a;
    asm("{ .reg .u64 t; cvta.to.shared.u64 t, %1; cvt.u32.u64 %0, t; }" : "=r"(a) : "l"(p));
    return a;
}
__device__ __forceinline__ void cp_async16(uint32_t dst, const void* src) {
    asm volatile("cp.async.cg.shared.global [%0], [%1], 16;" :: "r"(dst), "l"(src));
}
__device__ __forceinline__ void cp_commit() {
    asm volatile("cp.async.commit_group;" ::: "memory");
}
template<int N>
__device__ __forceinline__ void cp_wait() {
    asm volatile("cp.async.wait_group %0;" :: "n"(N) : "memory");
}
__device__ __forceinline__ void ldsm_x4(uint32_t& r0, uint32_t& r1, uint32_t& r2, uint32_t& r3, uint32_t a) {
    asm volatile("ldmatrix.sync.aligned.m8n8.x4.shared.b16 {%0,%1,%2,%3}, [%4];"
                 : "=r"(r0), "=r"(r1), "=r"(r2), "=r"(r3) : "r"(a));
}
__device__ __forceinline__ void ldsm_x2(uint32_t& r0, uint32_t& r1, uint32_t a) {
    asm volatile("ldmatrix.sync.aligned.m8n8.x2.shared.b16 {%0,%1}, [%2];"
                 : "=r"(r0), "=r"(r1) : "r"(a));
}
__device__ __forceinline__ void mma_f16(float* c, const uint32_t* a, const uint32_t* b) {
    asm volatile("mma.sync.aligned.m16n8k16.row.col.f32.f16.f16.f32 "
                 "{%0,%1,%2,%3}, {%4,%5,%6,%7}, {%8,%9}, {%0,%1,%2,%3};"
                 : "+f"(c[0]), "+f"(c[1]), "+f"(c[2]), "+f"(c[3])
                 : "r"(a[0]), "r"(a[1]), "r"(a[2]), "r"(a[3]), "r"(b[0]), "r"(b[1]));
}
__device__ __forceinline__ uint32_t pack_h2(float x, float y) {
    __half2 t(__float2half(x), __float2half(y));
    return *(uint32_t*)&t;
}

// ============================================================
// Fused convert: x + 4 weights fp32 -> fp16, one launch
// ============================================================
#define NXF4 (MTOT*DM/4)     // 2097152
#define NWF4 (DM*DM/4)       // 1048576
__global__ __launch_bounds__(256)
void tohalf5_kernel(const float* __restrict__ x,
                    const float* __restrict__ w0, const float* __restrict__ w1,
                    const float* __restrict__ w2, const float* __restrict__ w3,
                    __half* __restrict__ dx, __half* __restrict__ dw)
{
    int i = blockIdx.x * 256 + threadIdx.x;
    const float* s; __half* d; int off;
    if (i < NXF4) { s = x; d = dx; off = i; }
    else {
        int j = i - NXF4;
        int t = j >> 20;
        off = j & (NWF4 - 1);
        s = (t == 0) ? w0 : (t == 1) ? w1 : (t == 2) ? w2 : w3;
        d = dw + (size_t)t * DM * DM;
    }
    float4 v = ((const float4*)s)[off];
    ((__half2*)d)[2*off]   = __half2(__float2half(v.x), __float2half(v.y));
    ((__half2*)d)[2*off+1] = __half2(__float2half(v.z), __float2half(v.w));
}

// ============================================================
// fp16 single-pass GEMM: C[M,N] = A[M,K] @ W[N,K]^T  (unchanged R11)
// ============================================================
#define BK 32
#define GSTR 80
#define GTILE (128*GSTR)
#define GSTAGE (2*GTILE)
#define GEMM_SMEM (2*GSTAGE)

template<int ADD_BIAS>
__global__ __launch_bounds__(256, 2)
void gemm_f16(const __half* __restrict__ A, const __half* __restrict__ B,
              const float* __restrict__ bias, float* __restrict__ C)
{
    extern __shared__ __align__(128) char gsm[];
    const uint32_t sb = smem_u32(gsm);
    const int tid = threadIdx.x, wid = tid >> 5, lane = tid & 31;
    const int bm = blockIdx.y * 128;
    const int bn = blockIdx.x * 128;
    const int warp_m = wid >> 2;
    const int warp_n = wid & 3;
    const uint32_t OFF_A = 0, OFF_B = GTILE;

    float acc[4][4][4];
#pragma unroll
    for (int i = 0; i < 4; i++)
#pragma unroll
        for (int j = 0; j < 4; j++)
#pragma unroll
            for (int r = 0; r < 4; r++) acc[i][j][r] = 0.f;

    auto issue = [&](int c, int buf) {
        uint32_t st = sb + buf * GSTAGE;
        int k0 = c * BK;
#pragma unroll
        for (int t = 0; t < 2; ++t) {
            int i = tid * 2 + t;
            int row = i >> 2, seg = i & 3;
            uint32_t dst = (uint32_t)(row * GSTR + seg * 16);
            cp_async16(st + OFF_A + dst, (const char*)(A + (size_t)(bm + row)*DM + k0) + seg*16);
            cp_async16(st + OFF_B + dst, (const char*)(B + (size_t)(bn + row)*DM + k0) + seg*16);
        }
        cp_commit();
    };

    issue(0, 0);

    const uint32_t a_base = (uint32_t)((warp_m*64 + (lane & 15)) * GSTR + (lane >> 4) * 16);
    const uint32_t b_base = (uint32_t)((warp_n*32 + (lane & 7)) * GSTR + ((lane >> 3) & 1) * 16);

    const int NCH = DM / BK;
    for (int c = 0; c < NCH; ++c) {
        int buf = c & 1;
        if (c + 1 < NCH) { issue(c + 1, buf ^ 1); cp_wait<1>(); }
        else             { cp_wait<0>(); }
        __syncthreads();

        uint32_t st = sb + buf * GSTAGE;
#pragma unroll
        for (int kk = 0; kk < 2; ++kk) {
            uint32_t af[4][4], bf[4][2];
#pragma unroll
            for (int am = 0; am < 4; ++am)
                ldsm_x4(af[am][0], af[am][1], af[am][2], af[am][3],
                        st + OFF_A + a_base + am*16*GSTR + kk*32);
#pragma unroll
            for (int bt = 0; bt < 4; ++bt)
                ldsm_x2(bf[bt][0], bf[bt][1], st + OFF_B + b_base + bt*8*GSTR + kk*32);
#pragma unroll
            for (int am = 0; am < 4; ++am)
#pragma unroll
                for (int bt = 0; bt < 4; ++bt)
                    mma_f16(acc[am][bt], af[am], bf[bt]);
        }
        __syncthreads();
    }

    const int m_base = bm + warp_m*64;
    const int n_base = bn + warp_n*32;
#pragma unroll
    for (int am = 0; am < 4; ++am) {
#pragma unroll
        for (int bt = 0; bt < 4; ++bt) {
            int col = n_base + bt*8 + (lane & 3)*2;
            int r0 = m_base + am*16 + (lane >> 2);
            float b0 = 0.f, b1 = 0.f;
            if (ADD_BIAS) { b0 = bias[col]; b1 = bias[col+1]; }
            *(float2*)(C + (size_t)r0*DM + col) =
                make_float2(acc[am][bt][0] + b0, acc[am][bt][1] + b1);
            *(float2*)(C + (size_t)(r0+8)*DM + col) =
                make_float2(acc[am][bt][2] + b0, acc[am][bt][3] + b1);
        }
    }
}

// ============================================================
// RoPE + split (unchanged R11)
// ============================================================
__global__ __launch_bounds__(256)
void rope_split_kernel()
{
    int idx = blockIdx.x * blockDim.x + threadIdx.x;
    const int total = BH*SEQ*64;
    if (idx >= total) return;
    int i  = idx & 63;
    int s  = (idx >> 6) & (SEQ-1);
    int bh = idx >> 17;
    int b = bh >> 4, h = bh & 15;
    size_t src = ((size_t)b*SEQ + s)*DM + h*DKH + 2*i;
    size_t dst = ((size_t)bh*SEQ + s)*DKH + 2*i;

    float freq = powf(10000.f, -((float)(2*i)) / 128.f);
    float ang  = (float)s * freq;
    float sn, cs;
    sincosf(ang, &sn, &cs);

    float qe = g_q[src], qo = g_q[src+1];
    float q0 = qe*cs - qo*sn, q1 = qe*sn + qo*cs;
    float ke = g_k[src], ko = g_k[src+1];
    float k0 = ke*cs - ko*sn, k1 = ke*sn + ko*cs;

    __half qh0 = __float2half(q0), qh1 = __float2half(q1);
    *(__half2*)&g_qh[dst] = __half2(qh0, qh1);
    *(__half2*)&g_ql[dst] = __half2(__float2half(q0 - __half2float(qh0)),
                                    __float2half(q1 - __half2float(qh1)));
    *(__half2*)&g_kh[dst] = __half2(__float2half(k0), __float2half(k1));
}

// ============================================================
// V transpose (unchanged R11)
// ============================================================
__global__ __launch_bounds__(256)
void vsplit_kernel()
{
    __shared__ float t[32][33];
    int dk0 = blockIdx.x * 32;
    int s0  = blockIdx.y * 32;
    int bh  = blockIdx.z;
    int b = bh >> 4, h = bh & 15;
    int tx = threadIdx.x & 31, ty = threadIdx.x >> 5;
#pragma unroll
    for (int r = 0; r < 4; ++r)
        t[ty + 8*r][tx] = g_v[((size_t)(b*SEQ) + s0 + ty + 8*r)*DM + h*DKH + dk0 + tx];
    __syncthreads();
#pragma unroll
    for (int r = 0; r < 4; ++r) {
        int dk = ty + 8*r;
        g_vth[((size_t)bh*DKH + dk0 + dk)*SEQ + s0 + tx] = __float2half(t[tx][dk]);
    }
}

// ============================================================
// Flash attention fp16, causal, KV tile 128, diagonal triangle skip.
// CTA: 128 q-rows x 128 kv-cols.  8 warps x 16 q-rows.
// Writes fp16 c16 directly.
// ============================================================
#define KSTRB 272                      // 128 fp16 + 16B pad
#define AQH 0
#define AQL 34816
#define AST0 69632
#define ASTAGE 69632                   // K 34816 + VT 34816
#define AK  0
#define AVT 34816
#define ATTN_SMEM (AST0 + 2*ASTAGE)    // 208896

__global__ __launch_bounds__(256, 1)
void attn_mma(const __half* __restrict__ qh, const __half* __restrict__ ql,
              const __half* __restrict__ kh, const __half* __restrict__ vth,
              __half* __restrict__ c16)
{
    extern __shared__ __align__(128) char asm_[];
    const uint32_t sb = smem_u32(asm_);
    const int qt = (gridDim.x - 1) - blockIdx.x;   // longest CTAs first
    const int bh = blockIdx.y;
    const int tid = threadIdx.x, warp = tid >> 5, lane = tid & 31;
    const int b = bh >> 4, h = bh & 15;

    const __half* qhb = qh + ((size_t)bh*SEQ + qt*128)*DKH;
    const __half* qlb = ql + ((size_t)bh*SEQ + qt*128)*DKH;
    const __half* khb = kh + (size_t)bh*SEQ*DKH;
    const __half* vhb = vth + (size_t)bh*DKH*SEQ;

    // Q tiles (hi, lo)
    for (int i = tid; i < 2048; i += 256) {
        int row = i >> 4, seg = i & 15;
        uint32_t dst = (uint32_t)(row * KSTRB + seg * 16);
        cp_async16(sb + AQH + dst, (const char*)(qhb + (size_t)row*DKH) + seg*16);
        cp_async16(sb + AQL + dst, (const char*)(qlb + (size_t)row*DKH) + seg*16);
    }
    cp_commit();

    auto issue_kv = [&](int kt, int buf) {
        uint32_t st = sb + AST0 + buf * ASTAGE;
        for (int i = tid; i < 2048; i += 256) {
            int row = i >> 4, seg = i & 15;
            cp_async16(st + AK + (uint32_t)(row * KSTRB + seg * 16),
                       (const char*)(khb + ((size_t)(kt*128) + row)*DKH) + seg*16);
        }
        for (int i = tid; i < 2048; i += 256) {
            int row = i >> 4, seg = i & 15;
            cp_async16(st + AVT + (uint32_t)(row * KSTRB + seg * 16),
                       (const char*)(vhb + (size_t)row*SEQ + kt*128) + seg*16);
        }
        cp_commit();
    };

    const int nkt = qt + 1;
    issue_kv(0, 0);

    float o[16][4];
#pragma unroll
    for (int i = 0; i < 16; i++)
#pragma unroll
        for (int j = 0; j < 4; j++) o[i][j] = 0.f;
    float m_[2] = {-1e30f, -1e30f};
    float l_[2] = {0.f, 0.f};

    const float scl = 0.08838834764831845f;
    const int row0g = qt*128 + warp*16 + (lane >> 2);

    const uint32_t a_off = (uint32_t)((warp*16 + (lane & 15)) * KSTRB + (lane >> 4) * 16);
    const uint32_t kb_rowsel = (uint32_t)((((lane >> 3) & 1) * 8 + (lane & 7)));
    const uint32_t kseg = (uint32_t)((lane >> 4) * 16);

    for (int kt = 0; kt < nkt; ++kt) {
        int buf = kt & 1;
        if (kt + 1 < nkt) { issue_kv(kt + 1, buf ^ 1); cp_wait<1>(); }
        else              { cp_wait<0>(); }
        __syncthreads();

        uint32_t st = sb + AST0 + buf * ASTAGE;
        const bool diag = (kt == qt);
        const int pmax = diag ? warp : 7;   // triangle skip on diagonal tile

        // ---- S = Q K^T (Q hi+lo, K single) ----
        float s_[16][4];
#pragma unroll
        for (int i = 0; i < 16; i++)
#pragma unroll
            for (int j = 0; j < 4; j++) s_[i][j] = 0.f;

#pragma unroll
        for (int ks = 0; ks < 8; ++ks) {
            uint32_t aH[4], aL[4];
            ldsm_x4(aH[0], aH[1], aH[2], aH[3], sb + AQH + a_off + ks*32);
            ldsm_x4(aL[0], aL[1], aL[2], aL[3], sb + AQL + a_off + ks*32);
#pragma unroll
            for (int p = 0; p < 8; ++p) {
                if (p <= pmax) {
                    uint32_t kaddr = st + AK + (uint32_t)((p*16 + kb_rowsel) * KSTRB) + ks*32 + kseg;
                    uint32_t r0, r1, r2, r3;
                    ldsm_x4(r0, r1, r2, r3, kaddr);
                    uint32_t bh0[2] = {r0, r2}, bh1[2] = {r1, r3};
                    mma_f16(s_[2*p],   aH, bh0);
                    mma_f16(s_[2*p+1], aH, bh1);
                    mma_f16(s_[2*p],   aL, bh0);
                    mma_f16(s_[2*p+1], aL, bh1);
                }
            }
        }

        // ---- scale + causal mask (diagonal tile only) ----
#pragma unroll
        for (int nt = 0; nt < 16; ++nt) {
            int colg = kt*128 + nt*8 + (lane & 3)*2;
#pragma unroll
            for (int j = 0; j < 4; ++j) {
                float sv = s_[nt][j] * scl;
                if (diag) {
                    int r = row0g + ((j >> 1) << 3);
                    int c = colg + (j & 1);
                    if (c > r) sv = -1e30f;
                }
                s_[nt][j] = sv;
            }
        }

        // ---- online softmax ----
        float corr[2];
#pragma unroll
        for (int r = 0; r < 2; ++r) {
            float mx = m_[r];
#pragma unroll
            for (int nt = 0; nt < 16; ++nt)
                mx = fmaxf(mx, fmaxf(s_[nt][2*r], s_[nt][2*r+1]));
            mx = fmaxf(mx, __shfl_xor_sync(0xffffffffu, mx, 1));
            mx = fmaxf(mx, __shfl_xor_sync(0xffffffffu, mx, 2));
            corr[r] = __expf(m_[r] - mx);
            m_[r] = mx;
            float sum = 0.f;
#pragma unroll
            for (int nt = 0; nt < 16; ++nt) {
                float p0 = __expf(s_[nt][2*r]   - mx);
                float p1 = __expf(s_[nt][2*r+1] - mx);
                s_[nt][2*r] = p0; s_[nt][2*r+1] = p1;
                sum += p0 + p1;
            }
            sum += __shfl_xor_sync(0xffffffffu, sum, 1);
            sum += __shfl_xor_sync(0xffffffffu, sum, 2);
            l_[r] = l_[r]*corr[r] + sum;
        }

        // ---- rescale O ----
#pragma unroll
        for (int dt = 0; dt < 16; ++dt) {
            o[dt][0] *= corr[0]; o[dt][1] *= corr[0];
            o[dt][2] *= corr[1]; o[dt][3] *= corr[1];
        }

        // ---- O += P V (P hi+lo, V single); triangle skip on diagonal ----
#pragma unroll
        for (int kk = 0; kk < 8; ++kk) {
            if (kk <= pmax) {
                uint32_t aP[4], aPl[4];
#pragma unroll
                for (int half_ : {0, 1}) {
                    int nt = 2*kk + half_;
                    float p0 = s_[nt][0], p1 = s_[nt][1], p2 = s_[nt][2], p3 = s_[nt][3];
                    __half h0 = __float2half(p0), h1 = __float2half(p1);
                    __half h2 = __float2half(p2), h3 = __float2half(p3);
                    aP[2*half_]   = pack_h2(p0, p1);
                    aP[2*half_+1] = pack_h2(p2, p3);
                    aPl[2*half_]   = pack_h2(p0 - __half2float(h0), p1 - __half2float(h1));
                    aPl[2*half_+1] = pack_h2(p2 - __half2float(h2), p3 - __half2float(h3));
                }
#pragma unroll
                for (int p = 0; p < 8; ++p) {
                    uint32_t vaddr = st + AVT + (uint32_t)((p*16 + kb_rowsel) * KSTRB) + kk*32 + kseg;
                    uint32_t r0, r1, r2, r3;
                    ldsm_x4(r0, r1, r2, r3, vaddr);
                    uint32_t vh0[2] = {r0, r2}, vh1[2] = {r1, r3};
                    mma_f16(o[2*p],   aP,  vh0);
                    mma_f16(o[2*p+1], aP,  vh1);
                    mma_f16(o[2*p],   aPl, vh0);
                    mma_f16(o[2*p+1], aPl, vh1);
                }
            }
        }
        __syncthreads();
    }

    // ---- finalize: write fp16 ctx directly ----
    float inv0 = 1.0f / l_[0], inv1 = 1.0f / l_[1];
    int r0 = qt*128 + warp*16 + (lane >> 2);
#pragma unroll
    for (int dt = 0; dt < 16; ++dt) {
        int col = h*DKH + dt*8 + (lane & 3)*2;
        *(__half2*)&c16[((size_t)(b*SEQ) + r0)*DM + col] =
            __half2(__float2half(o[dt][0]*inv0), __float2half(o[dt][1]*inv0));
        *(__half2*)&c16[((size_t)(b*SEQ) + r0 + 8)*DM + col] =
            __half2(__float2half(o[dt][2]*inv1), __float2half(o[dt][3]*inv1));
    }
}

// ============================================================
extern "C" void kernel_launch(void* const* d_in, const int* in_sizes, int n_in,
                              void* d_out, int out_size)
{
    const float* x  = (const float*)d_in[0];
    const float* wq = (const float*)d_in[1];
    const float* wk = (const float*)d_in[2];
    const float* wv = (const float*)d_in[3];
    const float* wo = (const float*)d_in[4];
    const float* bo = (const float*)d_in[5];
    float* out = (float*)d_out;

    float *q, *k, *v;
    __half *x16, *w16, *c16, *qh, *ql, *kh, *vth;
    cudaGetSymbolAddress((void**)&q,   g_q);
    cudaGetSymbolAddress((void**)&k,   g_k);
    cudaGetSymbolAddress((void**)&v,   g_v);
    cudaGetSymbolAddress((void**)&x16, g_x16);
    cudaGetSymbolAddress((void**)&w16, g_w16);
    cudaGetSymbolAddress((void**)&c16, g_c16);
    cudaGetSymbolAddress((void**)&qh,  g_qh);
    cudaGetSymbolAddress((void**)&ql,  g_ql);
    cudaGetSymbolAddress((void**)&kh,  g_kh);
    cudaGetSymbolAddress((void**)&vth, g_vth);

    cudaFuncSetAttribute(gemm_f16<0>, cudaFuncAttributeMaxDynamicSharedMemorySize, GEMM_SMEM);
    cudaFuncSetAttribute(gemm_f16<1>, cudaFuncAttributeMaxDynamicSharedMemorySize, GEMM_SMEM);
    cudaFuncSetAttribute(attn_mma, cudaFuncAttributeMaxDynamicSharedMemorySize, ATTN_SMEM);

    // fused converts: x + 4 weights
    tohalf5_kernel<<<(NXF4 + 4*NWF4)/256, 256>>>(x, wq, wk, wv, wo, x16, w16);

    dim3 gg(DM/128, MTOT/128);   // (16, 32)
    gemm_f16<0><<<gg, 256, GEMM_SMEM>>>(x16, w16 + 0*(size_t)DM*DM, nullptr, q);
    gemm_f16<0><<<gg, 256, GEMM_SMEM>>>(x16, w16 + 1*(size_t)DM*DM, nullptr, k);
    gemm_f16<0><<<gg, 256, GEMM_SMEM>>>(x16, w16 + 2*(size_t)DM*DM, nullptr, v);

    rope_split_kernel<<<(BH*SEQ*64 + 255)/256, 256>>>();
    vsplit_kernel<<<dim3(DKH/32, SEQ/32, BH), 256>>>();

    attn_mma<<<dim3(SEQ/128, BH), 256, ATTN_SMEM>>>(qh, ql, kh, vth, c16);

    gemm_f16<1><<<gg, 256, GEMM_SMEM>>>(c16, w16 + 3*(size_t)DM*DM, bo, out);
}

// round 14
// speedup vs baseline: 1.1149x; 1.1149x over previous
#include <cuda_runtime.h>
#include <cuda_fp16.h>
#include <math.h>
#include <stdint.h>

#define BATCH 2
#define SEQ   2048
#define DM    2048
#define NH    16
#define DKH   128
#define MTOT  (BATCH*SEQ)   // 4096
#define BH    (BATCH*NH)    // 32

// ---- scratch (device globals) ----
__device__ float g_q[MTOT*DM];
__device__ float g_k[MTOT*DM];
__device__ float g_v[MTOT*DM];
__device__ __half g_x16[MTOT*DM];
__device__ __half g_w16[4][DM*DM];
__device__ __half g_c16[MTOT*DM];
// attention operands
__device__ __half g_qh[BH*SEQ*DKH];
__device__ __half g_ql[BH*SEQ*DKH];
__device__ __half g_kh[BH*SEQ*DKH];
__device__ __half g_vth[BH*DKH*SEQ];

// ============================================================
// helpers
// ============================================================
__device__ __forceinline__ uint32_t smem_u32(const void* p) {
    uint32_t a;
    asm("{ .reg .u64 t; cvta.to.shared.u64 t, %1; cvt.u32.u64 %0, t; }" : "=r"(a) : "l"(p));
    return a;
}
__device__ __forceinline__ void cp_async16(uint32_t dst, const void* src) {
    asm volatile("cp.async.cg.shared.global [%0], [%1], 16;" :: "r"(dst), "l"(src));
}
__device__ __forceinline__ void cp_commit() {
    asm volatile("cp.async.commit_group;" ::: "memory");
}
template<int N>
__device__ __forceinline__ void cp_wait() {
    asm volatile("cp.async.wait_group %0;" :: "n"(N) : "memory");
}
__device__ __forceinline__ void ldsm_x4(uint32_t& r0, uint32_t& r1, uint32_t& r2, uint32_t& r3, uint32_t a) {
    asm volatile("ldmatrix.sync.aligned.m8n8.x4.shared.b16 {%0,%1,%2,%3}, [%4];"
                 : "=r"(r0), "=r"(r1), "=r"(r2), "=r"(r3) : "r"(a));
}
__device__ __forceinline__ void ldsm_x2(uint32_t& r0, uint32_t& r1, uint32_t a) {
    asm volatile("ldmatrix.sync.aligned.m8n8.x2.shared.b16 {%0,%1}, [%2];"
                 : "=r"(r0), "=r"(r1) : "r"(a));
}
__device__ __forceinline__ void mma_f16(float* c, const uint32_t* a, const uint32_t* b) {
    asm volatile("mma.sync.aligned.m16n8k16.row.col.f32.f16.f16.f32 "
                 "{%0,%1,%2,%3}, {%4,%5,%6,%7}, {%8,%9}, {%0,%1,%2,%3};"
                 : "+f"(c[0]), "+f"(c[1]), "+f"(c[2]), "+f"(c[3])
                 : "r"(a[0]), "r"(a[1]), "r"(a[2]), "r"(a[3]), "r"(b[0]), "r"(b[1]));
}
__device__ __forceinline__ uint32_t pack_h2(float x, float y) {
    __half2 t(__float2half(x), __float2half(y));
    return *(uint32_t*)&t;
}

// ============================================================
// Fused convert: x + 4 weights fp32 -> fp16, one launch
// ============================================================
#define NXF4 (MTOT*DM/4)     // 2097152
#define NWF4 (DM*DM/4)       // 1048576
__global__ __launch_bounds__(256)
void tohalf5_kernel(const float* __restrict__ x,
                    const float* __restrict__ w0, const float* __restrict__ w1,
                    const float* __restrict__ w2, const float* __restrict__ w3,
                    __half* __restrict__ dx, __half* __restrict__ dw)
{
    int i = blockIdx.x * 256 + threadIdx.x;
    const float* s; __half* d; int off;
    if (i < NXF4) { s = x; d = dx; off = i; }
    else {
        int j = i - NXF4;
        int t = j >> 20;
        off = j & (NWF4 - 1);
        s = (t == 0) ? w0 : (t == 1) ? w1 : (t == 2) ? w2 : w3;
        d = dw + (size_t)t * DM * DM;
    }
    float4 v = ((const float4*)s)[off];
    ((__half2*)d)[2*off]   = __half2(__float2half(v.x), __float2half(v.y));
    ((__half2*)d)[2*off+1] = __half2(__float2half(v.z), __float2half(v.w));
}

// ============================================================
// fp16 GEMM core, 3-stage cp.async, one sync/iter.
// BM=BN=128, BK=32, 256 thr (8 warps 2x4), warp 64x32.
// ============================================================
#define BK 32
#define GSTR 80
#define GTILE (128*GSTR)
#define GSTAGE (2*GTILE)             // 20480: A, B
#define GEMM_SMEM (3*GSTAGE)         // 61440

template<int ADD_BIAS>
__device__ __forceinline__
void gemm_body(const __half* __restrict__ A, const __half* __restrict__ B,
               const float* __restrict__ bias, float* __restrict__ C,
               int bm, int bn)
{
    extern __shared__ __align__(128) char gsm[];
    const uint32_t sb = smem_u32(gsm);
    const int tid = threadIdx.x, wid = tid >> 5, lane = tid & 31;
    const int warp_m = wid >> 2;
    const int warp_n = wid & 3;
    const uint32_t OFF_A = 0, OFF_B = GTILE;

    float acc[4][4][4];
#pragma unroll
    for (int i = 0; i < 4; i++)
#pragma unroll
        for (int j = 0; j < 4; j++)
#pragma unroll
            for (int r = 0; r < 4; r++) acc[i][j][r] = 0.f;

    auto issue = [&](int c, int buf) {
        uint32_t st = sb + buf * GSTAGE;
        int k0 = c * BK;
#pragma unroll
        for (int t = 0; t < 2; ++t) {
            int i = tid * 2 + t;
            int row = i >> 2, seg = i & 3;
            uint32_t dst = (uint32_t)(row * GSTR + seg * 16);
            cp_async16(st + OFF_A + dst, (const char*)(A + (size_t)(bm + row)*DM + c*BK) + seg*16);
            cp_async16(st + OFF_B + dst, (const char*)(B + (size_t)(bn + row)*DM + c*BK) + seg*16);
        }
        cp_commit();
        (void)k0;
    };

    issue(0, 0);
    issue(1, 1);

    const uint32_t a_base = (uint32_t)((warp_m*64 + (lane & 15)) * GSTR + (lane >> 4) * 16);
    const uint32_t b_base = (uint32_t)((warp_n*32 + (lane & 7)) * GSTR + ((lane >> 3) & 1) * 16);

    const int NCH = DM / BK;    // 64
    int buf = 0;
    for (int c = 0; c < NCH; ++c) {
        if (c == NCH - 1) cp_wait<0>(); else cp_wait<1>();
        __syncthreads();   // stage c ready AND all warps done with buffer (c+2)%3
        if (c + 2 < NCH) issue(c + 2, (buf + 2 >= 3) ? buf - 1 : buf + 2);

        uint32_t st = sb + buf * GSTAGE;
#pragma unroll
        for (int kk = 0; kk < 2; ++kk) {
            uint32_t af[4][4], bf[4][2];
#pragma unroll
            for (int am = 0; am < 4; ++am)
                ldsm_x4(af[am][0], af[am][1], af[am][2], af[am][3],
                        st + OFF_A + a_base + am*16*GSTR + kk*32);
#pragma unroll
            for (int bt = 0; bt < 4; ++bt)
                ldsm_x2(bf[bt][0], bf[bt][1], st + OFF_B + b_base + bt*8*GSTR + kk*32);
#pragma unroll
            for (int am = 0; am < 4; ++am)
#pragma unroll
                for (int bt = 0; bt < 4; ++bt)
                    mma_f16(acc[am][bt], af[am], bf[bt]);
        }
        buf = (buf + 1 >= 3) ? 0 : buf + 1;
    }

    const int m_base = bm + warp_m*64;
    const int n_base = bn + warp_n*32;
#pragma unroll
    for (int am = 0; am < 4; ++am) {
#pragma unroll
        for (int bt = 0; bt < 4; ++bt) {
            int col = n_base + bt*8 + (lane & 3)*2;
            int r0 = m_base + am*16 + (lane >> 2);
            float b0 = 0.f, b1 = 0.f;
            if (ADD_BIAS) { b0 = bias[col]; b1 = bias[col+1]; }
            *(float2*)(C + (size_t)r0*DM + col) =
                make_float2(acc[am][bt][0] + b0, acc[am][bt][1] + b1);
            *(float2*)(C + (size_t)(r0+8)*DM + col) =
                make_float2(acc[am][bt][2] + b0, acc[am][bt][3] + b1);
        }
    }
}

// Merged QKV: grid (48, 32).  t = x>>4 selects weight/output.
__global__ __launch_bounds__(256, 2)
void gemm_qkv(const __half* __restrict__ A, const __half* __restrict__ W,
              float* __restrict__ q, float* __restrict__ k, float* __restrict__ v)
{
    int t = blockIdx.x >> 4;
    int bn = (blockIdx.x & 15) * 128;
    int bm = blockIdx.y * 128;
    const __half* B = W + (size_t)t * DM * DM;
    float* C = (t == 0) ? q : (t == 1) ? k : v;
    gemm_body<0>(A, B, nullptr, C, bm, bn);
}

// WO projection with bias: grid (16, 32).
__global__ __launch_bounds__(256, 2)
void gemm_wo(const __half* __restrict__ A, const __half* __restrict__ B,
             const float* __restrict__ bias, float* __restrict__ C)
{
    gemm_body<1>(A, B, bias, C, blockIdx.y * 128, blockIdx.x * 128);
}

// ============================================================
// RoPE + split (unchanged)
// ============================================================
__global__ __launch_bounds__(256)
void rope_split_kernel()
{
    int idx = blockIdx.x * blockDim.x + threadIdx.x;
    const int total = BH*SEQ*64;
    if (idx >= total) return;
    int i  = idx & 63;
    int s  = (idx >> 6) & (SEQ-1);
    int bh = idx >> 17;
    int b = bh >> 4, h = bh & 15;
    size_t src = ((size_t)b*SEQ + s)*DM + h*DKH + 2*i;
    size_t dst = ((size_t)bh*SEQ + s)*DKH + 2*i;

    float freq = powf(10000.f, -((float)(2*i)) / 128.f);
    float ang  = (float)s * freq;
    float sn, cs;
    sincosf(ang, &sn, &cs);

    float qe = g_q[src], qo = g_q[src+1];
    float q0 = qe*cs - qo*sn, q1 = qe*sn + qo*cs;
    float ke = g_k[src], ko = g_k[src+1];
    float k0 = ke*cs - ko*sn, k1 = ke*sn + ko*cs;

    __half qh0 = __float2half(q0), qh1 = __float2half(q1);
    *(__half2*)&g_qh[dst] = __half2(qh0, qh1);
    *(__half2*)&g_ql[dst] = __half2(__float2half(q0 - __half2float(qh0)),
                                    __float2half(q1 - __half2float(qh1)));
    *(__half2*)&g_kh[dst] = __half2(__float2half(k0), __float2half(k1));
}

// ============================================================
// V transpose (unchanged)
// ============================================================
__global__ __launch_bounds__(256)
void vsplit_kernel()
{
    __shared__ float t[32][33];
    int dk0 = blockIdx.x * 32;
    int s0  = blockIdx.y * 32;
    int bh  = blockIdx.z;
    int b = bh >> 4, h = bh & 15;
    int tx = threadIdx.x & 31, ty = threadIdx.x >> 5;
#pragma unroll
    for (int r = 0; r < 4; ++r)
        t[ty + 8*r][tx] = g_v[((size_t)(b*SEQ) + s0 + ty + 8*r)*DM + h*DKH + dk0 + tx];
    __syncthreads();
#pragma unroll
    for (int r = 0; r < 4; ++r) {
        int dk = ty + 8*r;
        g_vth[((size_t)bh*DKH + dk0 + dk)*SEQ + s0 + tx] = __float2half(t[tx][dk]);
    }
}

// ============================================================
// Flash attention fp16, causal (R11 shape: KV tile 64).
// CTA: 128 q-rows, 8 warps x 16 q-rows.  Writes fp16 c16.
// ============================================================
#define KSTRB 272                      // 128 fp16 row + 16B pad
#define VSTRB 144                      // 64 fp16 row + 16B pad
#define AQH 0
#define AQL 34816
#define AST0 69632
#define ASTAGE 35840                   // K 17408 + VT 18432
#define AK  0
#define AVT 17408
#define ATTN_SMEM (AST0 + 2*ASTAGE)    // 141312

__global__ __launch_bounds__(256, 1)
void attn_mma(const __half* __restrict__ qh, const __half* __restrict__ ql,
              const __half* __restrict__ kh, const __half* __restrict__ vth,
              __half* __restrict__ c16)
{
    extern __shared__ __align__(128) char asm_[];
    const uint32_t sb = smem_u32(asm_);
    const int qt = (gridDim.x - 1) - blockIdx.x;   // longest CTAs first
    const int bh = blockIdx.y;
    const int tid = threadIdx.x, warp = tid >> 5, lane = tid & 31;
    const int b = bh >> 4, h = bh & 15;

    const __half* qhb = qh + ((size_t)bh*SEQ + qt*128)*DKH;
    const __half* qlb = ql + ((size_t)bh*SEQ + qt*128)*DKH;
    const __half* khb = kh + (size_t)bh*SEQ*DKH;
    const __half* vhb = vth + (size_t)bh*DKH*SEQ;

    for (int i = tid; i < 2048; i += 256) {
        int row = i >> 4, seg = i & 15;
        uint32_t dst = (uint32_t)(row * KSTRB + seg * 16);
        cp_async16(sb + AQH + dst, (const char*)(qhb + (size_t)row*DKH) + seg*16);
        cp_async16(sb + AQL + dst, (const char*)(qlb + (size_t)row*DKH) + seg*16);
    }
    cp_commit();

    auto issue_kv = [&](int kt, int buf) {
        uint32_t st = sb + AST0 + buf * ASTAGE;
        for (int i = tid; i < 1024; i += 256) {
            int row = i >> 4, seg = i & 15;
            cp_async16(st + AK + (uint32_t)(row * KSTRB + seg * 16),
                       (const char*)(khb + ((size_t)(kt*64) + row)*DKH) + seg*16);
        }
        for (int i = tid; i < 1024; i += 256) {
            int row = i >> 3, seg = i & 7;
            cp_async16(st + AVT + (uint32_t)(row * VSTRB + seg * 16),
                       (const char*)(vhb + (size_t)row*SEQ + kt*64) + seg*16);
        }
        cp_commit();
    };

    const int nkt = 2*qt + 2;
    issue_kv(0, 0);

    float o[16][4];
#pragma unroll
    for (int i = 0; i < 16; i++)
#pragma unroll
        for (int j = 0; j < 4; j++) o[i][j] = 0.f;
    float m_[2] = {-1e30f, -1e30f};
    float l_[2] = {0.f, 0.f};

    const float scl = 0.08838834764831845f;
    const int row0g = qt*128 + warp*16 + (lane >> 2);

    const uint32_t a_off = (uint32_t)((warp*16 + (lane & 15)) * KSTRB + (lane >> 4) * 16);
    const uint32_t kb_rowsel = (uint32_t)((((lane >> 3) & 1) * 8 + (lane & 7)));
    const uint32_t kseg = (uint32_t)((lane >> 4) * 16);

    for (int kt = 0; kt < nkt; ++kt) {
        int buf = kt & 1;
        if (kt + 1 < nkt) { issue_kv(kt + 1, buf ^ 1); cp_wait<1>(); }
        else              { cp_wait<0>(); }
        __syncthreads();

        uint32_t st = sb + AST0 + buf * ASTAGE;

        float s_[8][4];
#pragma unroll
        for (int i = 0; i < 8; i++)
#pragma unroll
            for (int j = 0; j < 4; j++) s_[i][j] = 0.f;

#pragma unroll
        for (int ks = 0; ks < 8; ++ks) {
            uint32_t aH[4], aL[4];
            ldsm_x4(aH[0], aH[1], aH[2], aH[3], sb + AQH + a_off + ks*32);
            ldsm_x4(aL[0], aL[1], aL[2], aL[3], sb + AQL + a_off + ks*32);
#pragma unroll
            for (int p = 0; p < 4; ++p) {
                uint32_t kaddr = st + AK + (uint32_t)((p*16 + kb_rowsel) * KSTRB) + ks*32 + kseg;
                uint32_t r0, r1, r2, r3;
                ldsm_x4(r0, r1, r2, r3, kaddr);
                uint32_t bh0[2] = {r0, r2}, bh1[2] = {r1, r3};
                mma_f16(s_[2*p],   aH, bh0);
                mma_f16(s_[2*p+1], aH, bh1);
                mma_f16(s_[2*p],   aL, bh0);
                mma_f16(s_[2*p+1], aL, bh1);
            }
        }

        bool need_mask = (kt*64 + 63) > (qt*128 + warp*16);
#pragma unroll
        for (int nt = 0; nt < 8; ++nt) {
            int colg = kt*64 + nt*8 + (lane & 3)*2;
#pragma unroll
            for (int j = 0; j < 4; ++j) {
                float sv = s_[nt][j] * scl;
                if (need_mask) {
                    int r = row0g + ((j >> 1) << 3);
                    int c = colg + (j & 1);
                    if (c > r) sv = -1e30f;
                }
                s_[nt][j] = sv;
            }
        }

        float corr[2];
#pragma unroll
        for (int r = 0; r < 2; ++r) {
            float mx = m_[r];
#pragma unroll
            for (int nt = 0; nt < 8; ++nt)
                mx = fmaxf(mx, fmaxf(s_[nt][2*r], s_[nt][2*r+1]));
            mx = fmaxf(mx, __shfl_xor_sync(0xffffffffu, mx, 1));
            mx = fmaxf(mx, __shfl_xor_sync(0xffffffffu, mx, 2));
            corr[r] = __expf(m_[r] - mx);
            m_[r] = mx;
            float sum = 0.f;
#pragma unroll
            for (int nt = 0; nt < 8; ++nt) {
                float p0 = __expf(s_[nt][2*r]   - mx);
                float p1 = __expf(s_[nt][2*r+1] - mx);
                s_[nt][2*r] = p0; s_[nt][2*r+1] = p1;
                sum += p0 + p1;
            }
            sum += __shfl_xor_sync(0xffffffffu, sum, 1);
            sum += __shfl_xor_sync(0xffffffffu, sum, 2);
            l_[r] = l_[r]*corr[r] + sum;
        }

        uint32_t pH[8][2], pL[8][2];
#pragma unroll
        for (int nt = 0; nt < 8; ++nt) {
#pragma unroll
            for (int r = 0; r < 2; ++r) {
                float p0 = s_[nt][2*r], p1 = s_[nt][2*r+1];
                __half h0 = __float2half(p0), h1 = __float2half(p1);
                pH[nt][r] = pack_h2(p0, p1);
                pL[nt][r] = pack_h2(p0 - __half2float(h0), p1 - __half2float(h1));
            }
        }

#pragma unroll
        for (int dt = 0; dt < 16; ++dt) {
            o[dt][0] *= corr[0]; o[dt][1] *= corr[0];
            o[dt][2] *= corr[1]; o[dt][3] *= corr[1];
        }

#pragma unroll
        for (int kk = 0; kk < 4; ++kk) {
            uint32_t aP[4]  = {pH[2*kk][0], pH[2*kk][1], pH[2*kk+1][0], pH[2*kk+1][1]};
            uint32_t aPl[4] = {pL[2*kk][0], pL[2*kk][1], pL[2*kk+1][0], pL[2*kk+1][1]};
#pragma unroll
            for (int p = 0; p < 8; ++p) {
                uint32_t vaddr = st + AVT + (uint32_t)((p*16 + kb_rowsel) * VSTRB) + kk*32 + kseg;
                uint32_t r0, r1, r2, r3;
                ldsm_x4(r0, r1, r2, r3, vaddr);
                uint32_t vh0[2] = {r0, r2}, vh1[2] = {r1, r3};
                mma_f16(o[2*p],   aP,  vh0);
                mma_f16(o[2*p+1], aP,  vh1);
                mma_f16(o[2*p],   aPl, vh0);
                mma_f16(o[2*p+1], aPl, vh1);
            }
        }
        __syncthreads();
    }

    float inv0 = 1.0f / l_[0], inv1 = 1.0f / l_[1];
    int r0 = qt*128 + warp*16 + (lane >> 2);
#pragma unroll
    for (int dt = 0; dt < 16; ++dt) {
        int col = h*DKH + dt*8 + (lane & 3)*2;
        *(__half2*)&c16[((size_t)(b*SEQ) + r0)*DM + col] =
            __half2(__float2half(o[dt][0]*inv0), __float2half(o[dt][1]*inv0));
        *(__half2*)&c16[((size_t)(b*SEQ) + r0 + 8)*DM + col] =
            __half2(__float2half(o[dt][2]*inv1), __float2half(o[dt][3]*inv1));
    }
}

// ============================================================
extern "C" void kernel_launch(void* const* d_in, const int* in_sizes, int n_in,
                              void* d_out, int out_size)
{
    const float* x  = (const float*)d_in[0];
    const float* wq = (const float*)d_in[1];
    const float* wk = (const float*)d_in[2];
    const float* wv = (const float*)d_in[3];
    const float* wo = (const float*)d_in[4];
    const float* bo = (const float*)d_in[5];
    float* out = (float*)d_out;

    float *q, *k, *v;
    __half *x16, *w16, *c16, *qh, *ql, *kh, *vth;
    cudaGetSymbolAddress((void**)&q,   g_q);
    cudaGetSymbolAddress((void**)&k,   g_k);
    cudaGetSymbolAddress((void**)&v,   g_v);
    cudaGetSymbolAddress((void**)&x16, g_x16);
    cudaGetSymbolAddress((void**)&w16, g_w16);
    cudaGetSymbolAddress((void**)&c16, g_c16);
    cudaGetSymbolAddress((void**)&qh,  g_qh);
    cudaGetSymbolAddress((void**)&ql,  g_ql);
    cudaGetSymbolAddress((void**)&kh,  g_kh);
    cudaGetSymbolAddress((void**)&vth, g_vth);

    cudaFuncSetAttribute(gemm_qkv, cudaFuncAttributeMaxDynamicSharedMemorySize, GEMM_SMEM);
    cudaFuncSetAttribute(gemm_wo,  cudaFuncAttributeMaxDynamicSharedMemorySize, GEMM_SMEM);
    cudaFuncSetAttribute(attn_mma, cudaFuncAttributeMaxDynamicSharedMemorySize, ATTN_SMEM);

    tohalf5_kernel<<<(NXF4 + 4*NWF4)/256, 256>>>(x, wq, wk, wv, wo, x16, w16);

    gemm_qkv<<<dim3(48, 32), 256, GEMM_SMEM>>>(x16, w16, q, k, v);

    rope_split_kernel<<<(BH*SEQ*64 + 255)/256, 256>>>();
    vsplit_kernel<<<dim3(DKH/32, SEQ/32, BH), 256>>>();

    attn_mma<<<dim3(SEQ/128, BH), 256, ATTN_SMEM>>>(qh, ql, kh, vth, c16);

    gemm_wo<<<dim3(16, 32), 256, GEMM_SMEM>>>(c16, w16 + 3*(size_t)DM*DM, bo, out);
}

// round 15
// speedup vs baseline: 1.2395x; 1.1117x over previous
#include <cuda_runtime.h>
#include <cuda_fp16.h>
#include <math.h>
#include <stdint.h>

#define BATCH 2
#define SEQ   2048
#define DM    2048
#define NH    16
#define DKH   128
#define MTOT  (BATCH*SEQ)   // 4096
#define BH    (BATCH*NH)    // 32

// ---- scratch (device globals) ----
__device__ float g_q[MTOT*DM];
__device__ float g_k[MTOT*DM];
__device__ float g_v[MTOT*DM];
__device__ __half g_x16[MTOT*DM];
__device__ __half g_w16[4][DM*DM];
__device__ __half g_c16[MTOT*DM];
// attention operands
__device__ __half g_qh[BH*SEQ*DKH];
__device__ __half g_ql[BH*SEQ*DKH];
__device__ __half g_kh[BH*SEQ*DKH];
__device__ __half g_vth[BH*DKH*SEQ];

// ============================================================
// helpers
// ============================================================
__device__ __forceinline__ uint32_t smem_u32(const void* p) {
    uint32_t a;
    asm("{ .reg .u64 t; cvta.to.shared.u64 t, %1; cvt.u32.u64 %0, t; }" : "=r"(a) : "l"(p));
    return a;
}
__device__ __forceinline__ void cp_async16(uint32_t dst, const void* src) {
    asm volatile("cp.async.cg.shared.global [%0], [%1], 16;" :: "r"(dst), "l"(src));
}
__device__ __forceinline__ void cp_commit() {
    asm volatile("cp.async.commit_group;" ::: "memory");
}
template<int N>
__device__ __forceinline__ void cp_wait() {
    asm volatile("cp.async.wait_group %0;" :: "n"(N) : "memory");
}
__device__ __forceinline__ void ldsm_x4(uint32_t& r0, uint32_t& r1, uint32_t& r2, uint32_t& r3, uint32_t a) {
    asm volatile("ldmatrix.sync.aligned.m8n8.x4.shared.b16 {%0,%1,%2,%3}, [%4];"
                 : "=r"(r0), "=r"(r1), "=r"(r2), "=r"(r3) : "r"(a));
}
__device__ __forceinline__ void ldsm_x2(uint32_t& r0, uint32_t& r1, uint32_t a) {
    asm volatile("ldmatrix.sync.aligned.m8n8.x2.shared.b16 {%0,%1}, [%2];"
                 : "=r"(r0), "=r"(r1) : "r"(a));
}
__device__ __forceinline__ void mma_f16(float* c, const uint32_t* a, const uint32_t* b) {
    asm volatile("mma.sync.aligned.m16n8k16.row.col.f32.f16.f16.f32 "
                 "{%0,%1,%2,%3}, {%4,%5,%6,%7}, {%8,%9}, {%0,%1,%2,%3};"
                 : "+f"(c[0]), "+f"(c[1]), "+f"(c[2]), "+f"(c[3])
                 : "r"(a[0]), "r"(a[1]), "r"(a[2]), "r"(a[3]), "r"(b[0]), "r"(b[1]));
}
__device__ __forceinline__ uint32_t pack_h2(float x, float y) {
    __half2 t(__float2half(x), __float2half(y));
    return *(uint32_t*)&t;
}

// ============================================================
// Fused convert: x + 4 weights fp32 -> fp16, one launch
// ============================================================
#define NXF4 (MTOT*DM/4)     // 2097152
#define NWF4 (DM*DM/4)       // 1048576
__global__ __launch_bounds__(256)
void tohalf5_kernel(const float* __restrict__ x,
                    const float* __restrict__ w0, const float* __restrict__ w1,
                    const float* __restrict__ w2, const float* __restrict__ w3,
                    __half* __restrict__ dx, __half* __restrict__ dw)
{
    int i = blockIdx.x * 256 + threadIdx.x;
    const float* s; __half* d; int off;
    if (i < NXF4) { s = x; d = dx; off = i; }
    else {
        int j = i - NXF4;
        int t = j >> 20;
        off = j & (NWF4 - 1);
        s = (t == 0) ? w0 : (t == 1) ? w1 : (t == 2) ? w2 : w3;
        d = dw + (size_t)t * DM * DM;
    }
    float4 v = ((const float4*)s)[off];
    ((__half2*)d)[2*off]   = __half2(__float2half(v.x), __float2half(v.y));
    ((__half2*)d)[2*off+1] = __half2(__float2half(v.z), __float2half(v.w));
}

// ============================================================
// fp16 GEMM core: BK=64, XOR-swizzled smem (no pad), 3-stage
// cp.async, one sync/iter.  BM=BN=128, 256 thr (8 warps 2x4),
// warp 64x32.  B fragments loaded with ldmatrix.x4 (2 n-tiles).
// ============================================================
#define BK 64
#define GTILE 16384                  // 128 rows x 128 B
#define GSTAGE (2*GTILE)             // 32768: A, B
#define GEMM_SMEM (3*GSTAGE)         // 98304

template<int ADD_BIAS>
__device__ __forceinline__
void gemm_body(const __half* __restrict__ A, const __half* __restrict__ B,
               const float* __restrict__ bias, float* __restrict__ C,
               int bm, int bn)
{
    extern __shared__ __align__(128) char gsm[];
    const uint32_t sb = smem_u32(gsm);
    const int tid = threadIdx.x, wid = tid >> 5, lane = tid & 31;
    const int warp_m = wid >> 2;
    const int warp_n = wid & 3;
    const uint32_t OFF_A = 0, OFF_B = GTILE;

    float acc[4][4][4];
#pragma unroll
    for (int i = 0; i < 4; i++)
#pragma unroll
        for (int j = 0; j < 4; j++)
#pragma unroll
            for (int r = 0; r < 4; r++) acc[i][j][r] = 0.f;

    // loader: per stage, per tile: 128 rows x 8 segs = 1024 cp.async16.
    // thread does 4 for A + 4 for B.  dst swizzle: seg ^ (row&7).
    auto issue = [&](int c, int buf) {
        uint32_t st = sb + buf * GSTAGE;
        int k0 = c * BK;
#pragma unroll
        for (int t = 0; t < 4; ++t) {
            int i = tid * 4 + t;
            int row = i >> 3, seg = i & 7;
            uint32_t dst = (uint32_t)(row * 128 + ((seg ^ (row & 7)) << 4));
            cp_async16(st + OFF_A + dst, (const char*)(A + (size_t)(bm + row)*DM + k0) + seg*16);
            cp_async16(st + OFF_B + dst, (const char*)(B + (size_t)(bn + row)*DM + k0) + seg*16);
        }
        cp_commit();
    };

    issue(0, 0);
    issue(1, 1);

    // per-lane address components
    const uint32_t xr = (uint32_t)(lane & 7);                    // xor term (row&7)
    const uint32_t a_rowb = (uint32_t)((warp_m*64 + (lane & 15)) * 128);
    const uint32_t a_kh   = (uint32_t)(lane >> 4);               // k-half select
    const uint32_t b_rowb = (uint32_t)((warp_n*32 + (lane >> 4)*8 + (lane & 7)) * 128);
    const uint32_t b_kh   = (uint32_t)((lane >> 3) & 1);

    const int NCH = DM / BK;    // 32
    int buf = 0;
    for (int c = 0; c < NCH; ++c) {
        if (c == NCH - 1) cp_wait<0>(); else cp_wait<1>();
        __syncthreads();   // stage c ready AND all warps done with buffer (c+2)%3
        if (c + 2 < NCH) issue(c + 2, (buf + 2 >= 3) ? buf - 1 : buf + 2);

        uint32_t st = sb + buf * GSTAGE;
#pragma unroll
        for (int kk = 0; kk < 4; ++kk) {
            uint32_t aseg = ((uint32_t)(kk*2) + a_kh) ^ xr;
            uint32_t bseg = ((uint32_t)(kk*2) + b_kh) ^ xr;
            uint32_t af[4][4];
#pragma unroll
            for (int am = 0; am < 4; ++am)
                ldsm_x4(af[am][0], af[am][1], af[am][2], af[am][3],
                        st + OFF_A + a_rowb + (uint32_t)(am*16*128) + (aseg << 4));
#pragma unroll
            for (int bp = 0; bp < 2; ++bp) {
                uint32_t r0, r1, r2, r3;
                ldsm_x4(r0, r1, r2, r3,
                        st + OFF_B + b_rowb + (uint32_t)(bp*16*128) + (bseg << 4));
                uint32_t bf0[2] = {r0, r1}, bf1[2] = {r2, r3};
#pragma unroll
                for (int am = 0; am < 4; ++am) {
                    mma_f16(acc[am][2*bp],   af[am], bf0);
                    mma_f16(acc[am][2*bp+1], af[am], bf1);
                }
            }
        }
        buf = (buf + 1 >= 3) ? 0 : buf + 1;
    }

    const int m_base = bm + warp_m*64;
    const int n_base = bn + warp_n*32;
#pragma unroll
    for (int am = 0; am < 4; ++am) {
#pragma unroll
        for (int bt = 0; bt < 4; ++bt) {
            int col = n_base + bt*8 + (lane & 3)*2;
            int r0 = m_base + am*16 + (lane >> 2);
            float b0 = 0.f, b1 = 0.f;
            if (ADD_BIAS) { b0 = bias[col]; b1 = bias[col+1]; }
            *(float2*)(C + (size_t)r0*DM + col) =
                make_float2(acc[am][bt][0] + b0, acc[am][bt][1] + b1);
            *(float2*)(C + (size_t)(r0+8)*DM + col) =
                make_float2(acc[am][bt][2] + b0, acc[am][bt][3] + b1);
        }
    }
}

// Merged QKV: grid (48, 32).  t = x>>4 selects weight/output.
__global__ __launch_bounds__(256, 2)
void gemm_qkv(const __half* __restrict__ A, const __half* __restrict__ W,
              float* __restrict__ q, float* __restrict__ k, float* __restrict__ v)
{
    int t = blockIdx.x >> 4;
    int bn = (blockIdx.x & 15) * 128;
    int bm = blockIdx.y * 128;
    const __half* B = W + (size_t)t * DM * DM;
    float* C = (t == 0) ? q : (t == 1) ? k : v;
    gemm_body<0>(A, B, nullptr, C, bm, bn);
}

// WO projection with bias: grid (16, 32).
__global__ __launch_bounds__(256, 2)
void gemm_wo(const __half* __restrict__ A, const __half* __restrict__ B,
             const float* __restrict__ bias, float* __restrict__ C)
{
    gemm_body<1>(A, B, bias, C, blockIdx.y * 128, blockIdx.x * 128);
}

// ============================================================
// RoPE + split (unchanged)
// ============================================================
__global__ __launch_bounds__(256)
void rope_split_kernel()
{
    int idx = blockIdx.x * blockDim.x + threadIdx.x;
    const int total = BH*SEQ*64;
    if (idx >= total) return;
    int i  = idx & 63;
    int s  = (idx >> 6) & (SEQ-1);
    int bh = idx >> 17;
    int b = bh >> 4, h = bh & 15;
    size_t src = ((size_t)b*SEQ + s)*DM + h*DKH + 2*i;
    size_t dst = ((size_t)bh*SEQ + s)*DKH + 2*i;

    float freq = powf(10000.f, -((float)(2*i)) / 128.f);
    float ang  = (float)s * freq;
    float sn, cs;
    sincosf(ang, &sn, &cs);

    float qe = g_q[src], qo = g_q[src+1];
    float q0 = qe*cs - qo*sn, q1 = qe*sn + qo*cs;
    float ke = g_k[src], ko = g_k[src+1];
    float k0 = ke*cs - ko*sn, k1 = ke*sn + ko*cs;

    __half qh0 = __float2half(q0), qh1 = __float2half(q1);
    *(__half2*)&g_qh[dst] = __half2(qh0, qh1);
    *(__half2*)&g_ql[dst] = __half2(__float2half(q0 - __half2float(qh0)),
                                    __float2half(q1 - __half2float(qh1)));
    *(__half2*)&g_kh[dst] = __half2(__float2half(k0), __float2half(k1));
}

// ============================================================
// V transpose (unchanged)
// ============================================================
__global__ __launch_bounds__(256)
void vsplit_kernel()
{
    __shared__ float t[32][33];
    int dk0 = blockIdx.x * 32;
    int s0  = blockIdx.y * 32;
    int bh  = blockIdx.z;
    int b = bh >> 4, h = bh & 15;
    int tx = threadIdx.x & 31, ty = threadIdx.x >> 5;
#pragma unroll
    for (int r = 0; r < 4; ++r)
        t[ty + 8*r][tx] = g_v[((size_t)(b*SEQ) + s0 + ty + 8*r)*DM + h*DKH + dk0 + tx];
    __syncthreads();
#pragma unroll
    for (int r = 0; r < 4; ++r) {
        int dk = ty + 8*r;
        g_vth[((size_t)bh*DKH + dk0 + dk)*SEQ + s0 + tx] = __float2half(t[tx][dk]);
    }
}

// ============================================================
// Flash attention fp16, causal (R11 shape: KV tile 64).
// CTA: 128 q-rows, 8 warps x 16 q-rows.  Writes fp16 c16.
// ============================================================
#define KSTRB 272                      // 128 fp16 row + 16B pad
#define VSTRB 144                      // 64 fp16 row + 16B pad
#define AQH 0
#define AQL 34816
#define AST0 69632
#define ASTAGE 35840                   // K 17408 + VT 18432
#define AK  0
#define AVT 17408
#define ATTN_SMEM (AST0 + 2*ASTAGE)    // 141312

__global__ __launch_bounds__(256, 1)
void attn_mma(const __half* __restrict__ qh, const __half* __restrict__ ql,
              const __half* __restrict__ kh, const __half* __restrict__ vth,
              __half* __restrict__ c16)
{
    extern __shared__ __align__(128) char asm_[];
    const uint32_t sb = smem_u32(asm_);
    const int qt = (gridDim.x - 1) - blockIdx.x;   // longest CTAs first
    const int bh = blockIdx.y;
    const int tid = threadIdx.x, warp = tid >> 5, lane = tid & 31;
    const int b = bh >> 4, h = bh & 15;

    const __half* qhb = qh + ((size_t)bh*SEQ + qt*128)*DKH;
    const __half* qlb = ql + ((size_t)bh*SEQ + qt*128)*DKH;
    const __half* khb = kh + (size_t)bh*SEQ*DKH;
    const __half* vhb = vth + (size_t)bh*DKH*SEQ;

    for (int i = tid; i < 2048; i += 256) {
        int row = i >> 4, seg = i & 15;
        uint32_t dst = (uint32_t)(row * KSTRB + seg * 16);
        cp_async16(sb + AQH + dst, (const char*)(qhb + (size_t)row*DKH) + seg*16);
        cp_async16(sb + AQL + dst, (const char*)(qlb + (size_t)row*DKH) + seg*16);
    }
    cp_commit();

    auto issue_kv = [&](int kt, int buf) {
        uint32_t st = sb + AST0 + buf * ASTAGE;
        for (int i = tid; i < 1024; i += 256) {
            int row = i >> 4, seg = i & 15;
            cp_async16(st + AK + (uint32_t)(row * KSTRB + seg * 16),
                       (const char*)(khb + ((size_t)(kt*64) + row)*DKH) + seg*16);
        }
        for (int i = tid; i < 1024; i += 256) {
            int row = i >> 3, seg = i & 7;
            cp_async16(st + AVT + (uint32_t)(row * VSTRB + seg * 16),
                       (const char*)(vhb + (size_t)row*SEQ + kt*64) + seg*16);
        }
        cp_commit();
    };

    const int nkt = 2*qt + 2;
    issue_kv(0, 0);

    float o[16][4];
#pragma unroll
    for (int i = 0; i < 16; i++)
#pragma unroll
        for (int j = 0; j < 4; j++) o[i][j] = 0.f;
    float m_[2] = {-1e30f, -1e30f};
    float l_[2] = {0.f, 0.f};

    const float scl = 0.08838834764831845f;
    const int row0g = qt*128 + warp*16 + (lane >> 2);

    const uint32_t a_off = (uint32_t)((warp*16 + (lane & 15)) * KSTRB + (lane >> 4) * 16);
    const uint32_t kb_rowsel = (uint32_t)((((lane >> 3) & 1) * 8 + (lane & 7)));
    const uint32_t kseg = (uint32_t)((lane >> 4) * 16);

    for (int kt = 0; kt < nkt; ++kt) {
        int buf = kt & 1;
        if (kt + 1 < nkt) { issue_kv(kt + 1, buf ^ 1); cp_wait<1>(); }
        else              { cp_wait<0>(); }
        __syncthreads();

        uint32_t st = sb + AST0 + buf * ASTAGE;

        float s_[8][4];
#pragma unroll
        for (int i = 0; i < 8; i++)
#pragma unroll
            for (int j = 0; j < 4; j++) s_[i][j] = 0.f;

#pragma unroll
        for (int ks = 0; ks < 8; ++ks) {
            uint32_t aH[4], aL[4];
            ldsm_x4(aH[0], aH[1], aH[2], aH[3], sb + AQH + a_off + ks*32);
            ldsm_x4(aL[0], aL[1], aL[2], aL[3], sb + AQL + a_off + ks*32);
#pragma unroll
            for (int p = 0; p < 4; ++p) {
                uint32_t kaddr = st + AK + (uint32_t)((p*16 + kb_rowsel) * KSTRB) + ks*32 + kseg;
                uint32_t r0, r1, r2, r3;
                ldsm_x4(r0, r1, r2, r3, kaddr);
                uint32_t bh0[2] = {r0, r2}, bh1[2] = {r1, r3};
                mma_f16(s_[2*p],   aH, bh0);
                mma_f16(s_[2*p+1], aH, bh1);
                mma_f16(s_[2*p],   aL, bh0);
                mma_f16(s_[2*p+1], aL, bh1);
            }
        }

        bool need_mask = (kt*64 + 63) > (qt*128 + warp*16);
#pragma unroll
        for (int nt = 0; nt < 8; ++nt) {
            int colg = kt*64 + nt*8 + (lane & 3)*2;
#pragma unroll
            for (int j = 0; j < 4; ++j) {
                float sv = s_[nt][j] * scl;
                if (need_mask) {
                    int r = row0g + ((j >> 1) << 3);
                    int c = colg + (j & 1);
                    if (c > r) sv = -1e30f;
                }
                s_[nt][j] = sv;
            }
        }

        float corr[2];
#pragma unroll
        for (int r = 0; r < 2; ++r) {
            float mx = m_[r];
#pragma unroll
            for (int nt = 0; nt < 8; ++nt)
                mx = fmaxf(mx, fmaxf(s_[nt][2*r], s_[nt][2*r+1]));
            mx = fmaxf(mx, __shfl_xor_sync(0xffffffffu, mx, 1));
            mx = fmaxf(mx, __shfl_xor_sync(0xffffffffu, mx, 2));
            corr[r] = __expf(m_[r] - mx);
            m_[r] = mx;
            float sum = 0.f;
#pragma unroll
            for (int nt = 0; nt < 8; ++nt) {
                float p0 = __expf(s_[nt][2*r]   - mx);
                float p1 = __expf(s_[nt][2*r+1] - mx);
                s_[nt][2*r] = p0; s_[nt][2*r+1] = p1;
                sum += p0 + p1;
            }
            sum += __shfl_xor_sync(0xffffffffu, sum, 1);
            sum += __shfl_xor_sync(0xffffffffu, sum, 2);
            l_[r] = l_[r]*corr[r] + sum;
        }

        uint32_t pH[8][2], pL[8][2];
#pragma unroll
        for (int nt = 0; nt < 8; ++nt) {
#pragma unroll
            for (int r = 0; r < 2; ++r) {
                float p0 = s_[nt][2*r], p1 = s_[nt][2*r+1];
                __half h0 = __float2half(p0), h1 = __float2half(p1);
                pH[nt][r] = pack_h2(p0, p1);
                pL[nt][r] = pack_h2(p0 - __half2float(h0), p1 - __half2float(h1));
            }
        }

#pragma unroll
        for (int dt = 0; dt < 16; ++dt) {
            o[dt][0] *= corr[0]; o[dt][1] *= corr[0];
            o[dt][2] *= corr[1]; o[dt][3] *= corr[1];
        }

#pragma unroll
        for (int kk = 0; kk < 4; ++kk) {
            uint32_t aP[4]  = {pH[2*kk][0], pH[2*kk][1], pH[2*kk+1][0], pH[2*kk+1][1]};
            uint32_t aPl[4] = {pL[2*kk][0], pL[2*kk][1], pL[2*kk+1][0], pL[2*kk+1][1]};
#pragma unroll
            for (int p = 0; p < 8; ++p) {
                uint32_t vaddr = st + AVT + (uint32_t)((p*16 + kb_rowsel) * VSTRB) + kk*32 + kseg;
                uint32_t r0, r1, r2, r3;
                ldsm_x4(r0, r1, r2, r3, vaddr);
                uint32_t vh0[2] = {r0, r2}, vh1[2] = {r1, r3};
                mma_f16(o[2*p],   aP,  vh0);
                mma_f16(o[2*p+1], aP,  vh1);
                mma_f16(o[2*p],   aPl, vh0);
                mma_f16(o[2*p+1], aPl, vh1);
            }
        }
        __syncthreads();
    }

    float inv0 = 1.0f / l_[0], inv1 = 1.0f / l_[1];
    int r0 = qt*128 + warp*16 + (lane >> 2);
#pragma unroll
    for (int dt = 0; dt < 16; ++dt) {
        int col = h*DKH + dt*8 + (lane & 3)*2;
        *(__half2*)&c16[((size_t)(b*SEQ) + r0)*DM + col] =
            __half2(__float2half(o[dt][0]*inv0), __float2half(o[dt][1]*inv0));
        *(__half2*)&c16[((size_t)(b*SEQ) + r0 + 8)*DM + col] =
            __half2(__float2half(o[dt][2]*inv1), __float2half(o[dt][3]*inv1));
    }
}

// ============================================================
extern "C" void kernel_launch(void* const* d_in, const int* in_sizes, int n_in,
                              void* d_out, int out_size)
{
    const float* x  = (const float*)d_in[0];
    const float* wq = (const float*)d_in[1];
    const float* wk = (const float*)d_in[2];
    const float* wv = (const float*)d_in[3];
    const float* wo = (const float*)d_in[4];
    const float* bo = (const float*)d_in[5];
    float* out = (float*)d_out;

    float *q, *k, *v;
    __half *x16, *w16, *c16, *qh, *ql, *kh, *vth;
    cudaGetSymbolAddress((void**)&q,   g_q);
    cudaGetSymbolAddress((void**)&k,   g_k);
    cudaGetSymbolAddress((void**)&v,   g_v);
    cudaGetSymbolAddress((void**)&x16, g_x16);
    cudaGetSymbolAddress((void**)&w16, g_w16);
    cudaGetSymbolAddress((void**)&c16, g_c16);
    cudaGetSymbolAddress((void**)&qh,  g_qh);
    cudaGetSymbolAddress((void**)&ql,  g_ql);
    cudaGetSymbolAddress((void**)&kh,  g_kh);
    cudaGetSymbolAddress((void**)&vth, g_vth);

    cudaFuncSetAttribute(gemm_qkv, cudaFuncAttributeMaxDynamicSharedMemorySize, GEMM_SMEM);
    cudaFuncSetAttribute(gemm_wo,  cudaFuncAttributeMaxDynamicSharedMemorySize, GEMM_SMEM);
    cudaFuncSetAttribute(attn_mma, cudaFuncAttributeMaxDynamicSharedMemorySize, ATTN_SMEM);

    tohalf5_kernel<<<(NXF4 + 4*NWF4)/256, 256>>>(x, wq, wk, wv, wo, x16, w16);

    gemm_qkv<<<dim3(48, 32), 256, GEMM_SMEM>>>(x16, w16, q, k, v);

    rope_split_kernel<<<(BH*SEQ*64 + 255)/256, 256>>>();
    vsplit_kernel<<<dim3(DKH/32, SEQ/32, BH), 256>>>();

    attn_mma<<<dim3(SEQ/128, BH), 256, ATTN_SMEM>>>(qh, ql, kh, vth, c16);

    gemm_wo<<<dim3(16, 32), 256, GEMM_SMEM>>>(c16, w16 + 3*(size_t)DM*DM, bo, out);
}

// round 16
// speedup vs baseline: 1.2621x; 1.0183x over previous
#include <cuda_runtime.h>
#include <cuda_fp16.h>
#include <math.h>
#include <stdint.h>

#define BATCH 2
#define SEQ   2048
#define DM    2048
#define NH    16
#define DKH   128
#define MTOT  (BATCH*SEQ)   // 4096
#define BH    (BATCH*NH)    // 32

// ---- scratch (device globals) ----
__device__ __half g_x16[MTOT*DM];
__device__ __half g_w16[4][DM*DM];
__device__ __half g_c16[MTOT*DM];
__device__ __half g_v16[MTOT*DM];
// attention operands
__device__ __half g_qh[BH*SEQ*DKH];
__device__ __half g_ql[BH*SEQ*DKH];
__device__ __half g_kh[BH*SEQ*DKH];
__device__ __half g_vth[BH*DKH*SEQ];

// ============================================================
// helpers
// ============================================================
__device__ __forceinline__ uint32_t smem_u32(const void* p) {
    uint32_t a;
    asm("{ .reg .u64 t; cvta.to.shared.u64 t, %1; cvt.u32.u64 %0, t; }" : "=r"(a) : "l"(p));
    return a;
}
__device__ __forceinline__ void cp_async16(uint32_t dst, const void* src) {
    asm volatile("cp.async.cg.shared.global [%0], [%1], 16;" :: "r"(dst), "l"(src));
}
__device__ __forceinline__ void cp_commit() {
    asm volatile("cp.async.commit_group;" ::: "memory");
}
template<int N>
__device__ __forceinline__ void cp_wait() {
    asm volatile("cp.async.wait_group %0;" :: "n"(N) : "memory");
}
__device__ __forceinline__ void ldsm_x4(uint32_t& r0, uint32_t& r1, uint32_t& r2, uint32_t& r3, uint32_t a) {
    asm volatile("ldmatrix.sync.aligned.m8n8.x4.shared.b16 {%0,%1,%2,%3}, [%4];"
                 : "=r"(r0), "=r"(r1), "=r"(r2), "=r"(r3) : "r"(a));
}
__device__ __forceinline__ void mma_f16(float* c, const uint32_t* a, const uint32_t* b) {
    asm volatile("mma.sync.aligned.m16n8k16.row.col.f32.f16.f16.f32 "
                 "{%0,%1,%2,%3}, {%4,%5,%6,%7}, {%8,%9}, {%0,%1,%2,%3};"
                 : "+f"(c[0]), "+f"(c[1]), "+f"(c[2]), "+f"(c[3])
                 : "r"(a[0]), "r"(a[1]), "r"(a[2]), "r"(a[3]), "r"(b[0]), "r"(b[1]));
}
__device__ __forceinline__ uint32_t pack_h2(float x, float y) {
    __half2 t(__float2half(x), __float2half(y));
    return *(uint32_t*)&t;
}

// ============================================================
// Fused convert: x + 4 weights fp32 -> fp16, one launch
// ============================================================
#define NXF4 (MTOT*DM/4)
#define NWF4 (DM*DM/4)
__global__ __launch_bounds__(256)
void tohalf5_kernel(const float* __restrict__ x,
                    const float* __restrict__ w0, const float* __restrict__ w1,
                    const float* __restrict__ w2, const float* __restrict__ w3,
                    __half* __restrict__ dx, __half* __restrict__ dw)
{
    int i = blockIdx.x * 256 + threadIdx.x;
    const float* s; __half* d; int off;
    if (i < NXF4) { s = x; d = dx; off = i; }
    else {
        int j = i - NXF4;
        int t = j >> 20;
        off = j & (NWF4 - 1);
        s = (t == 0) ? w0 : (t == 1) ? w1 : (t == 2) ? w2 : w3;
        d = dw + (size_t)t * DM * DM;
    }
    float4 v = ((const float4*)s)[off];
    ((__half2*)d)[2*off]   = __half2(__float2half(v.x), __float2half(v.y));
    ((__half2*)d)[2*off+1] = __half2(__float2half(v.z), __float2half(v.w));
}

// ============================================================
// fp16 GEMM core: BK=64, XOR-swizzled smem, 3-stage cp.async.
// BM=BN=128, 256 thr (8 warps 2x4), warp 64x32.
// Computes acc; epilogue left to caller.
// ============================================================
#define BK 64
#define GTILE 16384
#define GSTAGE (2*GTILE)             // 32768
#define GEMM_SMEM (3*GSTAGE)         // 98304

__device__ __forceinline__
void gemm_core(const __half* __restrict__ A, const __half* __restrict__ B,
               int bm, int bn, float acc[4][4][4])
{
    extern __shared__ __align__(128) char gsm[];
    const uint32_t sb = smem_u32(gsm);
    const int tid = threadIdx.x, wid = tid >> 5, lane = tid & 31;
    const int warp_m = wid >> 2;
    const int warp_n = wid & 3;
    const uint32_t OFF_A = 0, OFF_B = GTILE;

#pragma unroll
    for (int i = 0; i < 4; i++)
#pragma unroll
        for (int j = 0; j < 4; j++)
#pragma unroll
            for (int r = 0; r < 4; r++) acc[i][j][r] = 0.f;

    auto issue = [&](int c, int buf) {
        uint32_t st = sb + buf * GSTAGE;
        int k0 = c * BK;
#pragma unroll
        for (int t = 0; t < 4; ++t) {
            int i = tid * 4 + t;
            int row = i >> 3, seg = i & 7;
            uint32_t dst = (uint32_t)(row * 128 + ((seg ^ (row & 7)) << 4));
            cp_async16(st + OFF_A + dst, (const char*)(A + (size_t)(bm + row)*DM + k0) + seg*16);
            cp_async16(st + OFF_B + dst, (const char*)(B + (size_t)(bn + row)*DM + k0) + seg*16);
        }
        cp_commit();
    };

    issue(0, 0);
    issue(1, 1);

    const uint32_t xr = (uint32_t)(lane & 7);
    const uint32_t a_rowb = (uint32_t)((warp_m*64 + (lane & 15)) * 128);
    const uint32_t a_kh   = (uint32_t)(lane >> 4);
    const uint32_t b_rowb = (uint32_t)((warp_n*32 + (lane >> 4)*8 + (lane & 7)) * 128);
    const uint32_t b_kh   = (uint32_t)((lane >> 3) & 1);

    const int NCH = DM / BK;    // 32
    int buf = 0;
    for (int c = 0; c < NCH; ++c) {
        if (c == NCH - 1) cp_wait<0>(); else cp_wait<1>();
        __syncthreads();
        if (c + 2 < NCH) issue(c + 2, (buf + 2 >= 3) ? buf - 1 : buf + 2);

        uint32_t st = sb + buf * GSTAGE;
#pragma unroll
        for (int kk = 0; kk < 4; ++kk) {
            uint32_t aseg = ((uint32_t)(kk*2) + a_kh) ^ xr;
            uint32_t bseg = ((uint32_t)(kk*2) + b_kh) ^ xr;
            uint32_t af[4][4];
#pragma unroll
            for (int am = 0; am < 4; ++am)
                ldsm_x4(af[am][0], af[am][1], af[am][2], af[am][3],
                        st + OFF_A + a_rowb + (uint32_t)(am*16*128) + (aseg << 4));
#pragma unroll
            for (int bp = 0; bp < 2; ++bp) {
                uint32_t r0, r1, r2, r3;
                ldsm_x4(r0, r1, r2, r3,
                        st + OFF_B + b_rowb + (uint32_t)(bp*16*128) + (bseg << 4));
                uint32_t bf0[2] = {r0, r1}, bf1[2] = {r2, r3};
#pragma unroll
                for (int am = 0; am < 4; ++am) {
                    mma_f16(acc[am][2*bp],   af[am], bf0);
                    mma_f16(acc[am][2*bp+1], af[am], bf1);
                }
            }
        }
        buf = (buf + 1 >= 3) ? 0 : buf + 1;
    }
}

// ============================================================
// Merged QKV with fused RoPE+split epilogue.
// grid (48, 32).  t = x>>4: 0=Q, 1=K, 2=V.  head h = x&15.
// Q: RoPE, split hi/lo -> qh, ql [bh][s][dk] fp16
// K: RoPE -> kh [bh][s][dk] fp16
// V: v16 [m][dm] fp16 (plain layout)
// ============================================================
__global__ __launch_bounds__(256, 2)
void gemm_qkv(const __half* __restrict__ A, const __half* __restrict__ W,
              __half* __restrict__ qh, __half* __restrict__ ql,
              __half* __restrict__ kh, __half* __restrict__ v16)
{
    int t = blockIdx.x >> 4;
    int h = blockIdx.x & 15;
    int bn = h * 128;
    int bm = blockIdx.y * 128;
    const __half* B = W + (size_t)t * DM * DM;

    float acc[4][4][4];
    gemm_core(A, B, bm, bn, acc);

    const int wid = threadIdx.x >> 5, lane = threadIdx.x & 31;
    const int warp_m = wid >> 2, warp_n = wid & 3;
    const int m_base = bm + warp_m*64;
    const int n_base = bn + warp_n*32;

    if (t == 2) {
        // V: plain fp16 store [m][dm]
#pragma unroll
        for (int am = 0; am < 4; ++am) {
#pragma unroll
            for (int bt = 0; bt < 4; ++bt) {
                int col = n_base + bt*8 + (lane & 3)*2;
                int r0 = m_base + am*16 + (lane >> 2);
                *(__half2*)&v16[(size_t)r0*DM + col] =
                    __half2(__float2half(acc[am][bt][0]), __float2half(acc[am][bt][1]));
                *(__half2*)&v16[(size_t)(r0+8)*DM + col] =
                    __half2(__float2half(acc[am][bt][2]), __float2half(acc[am][bt][3]));
            }
        }
    } else {
#pragma unroll
        for (int bt = 0; bt < 4; ++bt) {
            int col = n_base + bt*8 + (lane & 3)*2;
            int dk = col & 127;
            float freq = powf(10000.f, -((float)dk) / 128.f);
#pragma unroll
            for (int am = 0; am < 4; ++am) {
#pragma unroll
                for (int rr = 0; rr < 2; ++rr) {
                    int r = m_base + am*16 + (lane >> 2) + rr*8;
                    int s = r & (SEQ-1);
                    int b = r >> 11;
                    float v0 = acc[am][bt][2*rr], v1 = acc[am][bt][2*rr+1];
                    float sn, cs;
                    sincosf((float)s * freq, &sn, &cs);
                    float e0 = v0*cs - v1*sn;
                    float e1 = v0*sn + v1*cs;
                    size_t dst = (((size_t)(b*NH + h))*SEQ + s)*DKH + dk;
                    if (t == 0) {
                        __half h0 = __float2half(e0), h1 = __float2half(e1);
                        *(__half2*)&qh[dst] = __half2(h0, h1);
                        *(__half2*)&ql[dst] = __half2(__float2half(e0 - __half2float(h0)),
                                                      __float2half(e1 - __half2float(h1)));
                    } else {
                        *(__half2*)&kh[dst] = __half2(__float2half(e0), __float2half(e1));
                    }
                }
            }
        }
    }
}

// WO projection with bias: grid (16, 32).
__global__ __launch_bounds__(256, 2)
void gemm_wo(const __half* __restrict__ A, const __half* __restrict__ B,
             const float* __restrict__ bias, float* __restrict__ C)
{
    int bm = blockIdx.y * 128;
    int bn = blockIdx.x * 128;
    float acc[4][4][4];
    gemm_core(A, B, bm, bn, acc);

    const int wid = threadIdx.x >> 5, lane = threadIdx.x & 31;
    const int m_base = bm + (wid >> 2)*64;
    const int n_base = bn + (wid & 3)*32;
#pragma unroll
    for (int am = 0; am < 4; ++am) {
#pragma unroll
        for (int bt = 0; bt < 4; ++bt) {
            int col = n_base + bt*8 + (lane & 3)*2;
            int r0 = m_base + am*16 + (lane >> 2);
            float b0 = bias[col], b1 = bias[col+1];
            *(float2*)(C + (size_t)r0*DM + col) =
                make_float2(acc[am][bt][0] + b0, acc[am][bt][1] + b1);
            *(float2*)(C + (size_t)(r0+8)*DM + col) =
                make_float2(acc[am][bt][2] + b0, acc[am][bt][3] + b1);
        }
    }
}

// ============================================================
// V transpose: fp16 v16 [b][s][h*128+dk] -> fp16 [bh][dk][s]
// ============================================================
__global__ __launch_bounds__(256)
void vsplit_kernel()
{
    __shared__ float t[32][33];
    int dk0 = blockIdx.x * 32;
    int s0  = blockIdx.y * 32;
    int bh  = blockIdx.z;
    int b = bh >> 4, h = bh & 15;
    int tx = threadIdx.x & 31, ty = threadIdx.x >> 5;
#pragma unroll
    for (int r = 0; r < 4; ++r)
        t[ty + 8*r][tx] = __half2float(
            g_v16[((size_t)(b*SEQ) + s0 + ty + 8*r)*DM + h*DKH + dk0 + tx]);
    __syncthreads();
#pragma unroll
    for (int r = 0; r < 4; ++r) {
        int dk = ty + 8*r;
        g_vth[((size_t)bh*DKH + dk0 + dk)*SEQ + s0 + tx] = __float2half(t[tx][dk]);
    }
}

// ============================================================
// Flash attention fp16, causal (unchanged R15).
// ============================================================
#define KSTRB 272
#define VSTRB 144
#define AQH 0
#define AQL 34816
#define AST0 69632
#define ASTAGE 35840
#define AK  0
#define AVT 17408
#define ATTN_SMEM (AST0 + 2*ASTAGE)    // 141312

__global__ __launch_bounds__(256, 1)
void attn_mma(const __half* __restrict__ qh, const __half* __restrict__ ql,
              const __half* __restrict__ kh, const __half* __restrict__ vth,
              __half* __restrict__ c16)
{
    extern __shared__ __align__(128) char asm_[];
    const uint32_t sb = smem_u32(asm_);
    const int qt = (gridDim.x - 1) - blockIdx.x;
    const int bh = blockIdx.y;
    const int tid = threadIdx.x, warp = tid >> 5, lane = tid & 31;
    const int b = bh >> 4, h = bh & 15;

    const __half* qhb = qh + ((size_t)bh*SEQ + qt*128)*DKH;
    const __half* qlb = ql + ((size_t)bh*SEQ + qt*128)*DKH;
    const __half* khb = kh + (size_t)bh*SEQ*DKH;
    const __half* vhb = vth + (size_t)bh*DKH*SEQ;

    for (int i = tid; i < 2048; i += 256) {
        int row = i >> 4, seg = i & 15;
        uint32_t dst = (uint32_t)(row * KSTRB + seg * 16);
        cp_async16(sb + AQH + dst, (const char*)(qhb + (size_t)row*DKH) + seg*16);
        cp_async16(sb + AQL + dst, (const char*)(qlb + (size_t)row*DKH) + seg*16);
    }
    cp_commit();

    auto issue_kv = [&](int kt, int buf) {
        uint32_t st = sb + AST0 + buf * ASTAGE;
        for (int i = tid; i < 1024; i += 256) {
            int row = i >> 4, seg = i & 15;
            cp_async16(st + AK + (uint32_t)(row * KSTRB + seg * 16),
                       (const char*)(khb + ((size_t)(kt*64) + row)*DKH) + seg*16);
        }
        for (int i = tid; i < 1024; i += 256) {
            int row = i >> 3, seg = i & 7;
            cp_async16(st + AVT + (uint32_t)(row * VSTRB + seg * 16),
                       (const char*)(vhb + (size_t)row*SEQ + kt*64) + seg*16);
        }
        cp_commit();
    };

    const int nkt = 2*qt + 2;
    issue_kv(0, 0);

    float o[16][4];
#pragma unroll
    for (int i = 0; i < 16; i++)
#pragma unroll
        for (int j = 0; j < 4; j++) o[i][j] = 0.f;
    float m_[2] = {-1e30f, -1e30f};
    float l_[2] = {0.f, 0.f};

    const float scl = 0.08838834764831845f;
    const int row0g = qt*128 + warp*16 + (lane >> 2);

    const uint32_t a_off = (uint32_t)((warp*16 + (lane & 15)) * KSTRB + (lane >> 4) * 16);
    const uint32_t kb_rowsel = (uint32_t)((((lane >> 3) & 1) * 8 + (lane & 7)));
    const uint32_t kseg = (uint32_t)((lane >> 4) * 16);

    for (int kt = 0; kt < nkt; ++kt) {
        int buf = kt & 1;
        if (kt + 1 < nkt) { issue_kv(kt + 1, buf ^ 1); cp_wait<1>(); }
        else              { cp_wait<0>(); }
        __syncthreads();

        uint32_t st = sb + AST0 + buf * ASTAGE;

        float s_[8][4];
#pragma unroll
        for (int i = 0; i < 8; i++)
#pragma unroll
            for (int j = 0; j < 4; j++) s_[i][j] = 0.f;

#pragma unroll
        for (int ks = 0; ks < 8; ++ks) {
            uint32_t aH[4], aL[4];
            ldsm_x4(aH[0], aH[1], aH[2], aH[3], sb + AQH + a_off + ks*32);
            ldsm_x4(aL[0], aL[1], aL[2], aL[3], sb + AQL + a_off + ks*32);
#pragma unroll
            for (int p = 0; p < 4; ++p) {
                uint32_t kaddr = st + AK + (uint32_t)((p*16 + kb_rowsel) * KSTRB) + ks*32 + kseg;
                uint32_t r0, r1, r2, r3;
                ldsm_x4(r0, r1, r2, r3, kaddr);
                uint32_t bh0[2] = {r0, r2}, bh1[2] = {r1, r3};
                mma_f16(s_[2*p],   aH, bh0);
                mma_f16(s_[2*p+1], aH, bh1);
                mma_f16(s_[2*p],   aL, bh0);
                mma_f16(s_[2*p+1], aL, bh1);
            }
        }

        bool need_mask = (kt*64 + 63) > (qt*128 + warp*16);
#pragma unroll
        for (int nt = 0; nt < 8; ++nt) {
            int colg = kt*64 + nt*8 + (lane & 3)*2;
#pragma unroll
            for (int j = 0; j < 4; ++j) {
                float sv = s_[nt][j] * scl;
                if (need_mask) {
                    int r = row0g + ((j >> 1) << 3);
                    int c = colg + (j & 1);
                    if (c > r) sv = -1e30f;
                }
                s_[nt][j] = sv;
            }
        }

        float corr[2];
#pragma unroll
        for (int r = 0; r < 2; ++r) {
            float mx = m_[r];
#pragma unroll
            for (int nt = 0; nt < 8; ++nt)
                mx = fmaxf(mx, fmaxf(s_[nt][2*r], s_[nt][2*r+1]));
            mx = fmaxf(mx, __shfl_xor_sync(0xffffffffu, mx, 1));
            mx = fmaxf(mx, __shfl_xor_sync(0xffffffffu, mx, 2));
            corr[r] = __expf(m_[r] - mx);
            m_[r] = mx;
            float sum = 0.f;
#pragma unroll
            for (int nt = 0; nt < 8; ++nt) {
                float p0 = __expf(s_[nt][2*r]   - mx);
                float p1 = __expf(s_[nt][2*r+1] - mx);
                s_[nt][2*r] = p0; s_[nt][2*r+1] = p1;
                sum += p0 + p1;
            }
            sum += __shfl_xor_sync(0xffffffffu, sum, 1);
            sum += __shfl_xor_sync(0xffffffffu, sum, 2);
            l_[r] = l_[r]*corr[r] + sum;
        }

        uint32_t pH[8][2], pL[8][2];
#pragma unroll
        for (int nt = 0; nt < 8; ++nt) {
#pragma unroll
            for (int r = 0; r < 2; ++r) {
                float p0 = s_[nt][2*r], p1 = s_[nt][2*r+1];
                __half h0 = __float2half(p0), h1 = __float2half(p1);
                pH[nt][r] = pack_h2(p0, p1);
                pL[nt][r] = pack_h2(p0 - __half2float(h0), p1 - __half2float(h1));
            }
        }

#pragma unroll
        for (int dt = 0; dt < 16; ++dt) {
            o[dt][0] *= corr[0]; o[dt][1] *= corr[0];
            o[dt][2] *= corr[1]; o[dt][3] *= corr[1];
        }

#pragma unroll
        for (int kk = 0; kk < 4; ++kk) {
            uint32_t aP[4]  = {pH[2*kk][0], pH[2*kk][1], pH[2*kk+1][0], pH[2*kk+1][1]};
            uint32_t aPl[4] = {pL[2*kk][0], pL[2*kk][1], pL[2*kk+1][0], pL[2*kk+1][1]};
#pragma unroll
            for (int p = 0; p < 8; ++p) {
                uint32_t vaddr = st + AVT + (uint32_t)((p*16 + kb_rowsel) * VSTRB) + kk*32 + kseg;
                uint32_t r0, r1, r2, r3;
                ldsm_x4(r0, r1, r2, r3, vaddr);
                uint32_t vh0[2] = {r0, r2}, vh1[2] = {r1, r3};
                mma_f16(o[2*p],   aP,  vh0);
                mma_f16(o[2*p+1], aP,  vh1);
                mma_f16(o[2*p],   aPl, vh0);
                mma_f16(o[2*p+1], aPl, vh1);
            }
        }
        __syncthreads();
    }

    float inv0 = 1.0f / l_[0], inv1 = 1.0f / l_[1];
    int r0 = qt*128 + warp*16 + (lane >> 2);
#pragma unroll
    for (int dt = 0; dt < 16; ++dt) {
        int col = h*DKH + dt*8 + (lane & 3)*2;
        *(__half2*)&c16[((size_t)(b*SEQ) + r0)*DM + col] =
            __half2(__float2half(o[dt][0]*inv0), __float2half(o[dt][1]*inv0));
        *(__half2*)&c16[((size_t)(b*SEQ) + r0 + 8)*DM + col] =
            __half2(__float2half(o[dt][2]*inv1), __float2half(o[dt][3]*inv1));
    }
}

// ============================================================
extern "C" void kernel_launch(void* const* d_in, const int* in_sizes, int n_in,
                              void* d_out, int out_size)
{
    const float* x  = (const float*)d_in[0];
    const float* wq = (const float*)d_in[1];
    const float* wk = (const float*)d_in[2];
    const float* wv = (const float*)d_in[3];
    const float* wo = (const float*)d_in[4];
    const float* bo = (const float*)d_in[5];
    float* out = (float*)d_out;

    __half *x16, *w16, *c16, *v16, *qh, *ql, *kh, *vth;
    cudaGetSymbolAddress((void**)&x16, g_x16);
    cudaGetSymbolAddress((void**)&w16, g_w16);
    cudaGetSymbolAddress((void**)&c16, g_c16);
    cudaGetSymbolAddress((void**)&v16, g_v16);
    cudaGetSymbolAddress((void**)&qh,  g_qh);
    cudaGetSymbolAddress((void**)&ql,  g_ql);
    cudaGetSymbolAddress((void**)&kh,  g_kh);
    cudaGetSymbolAddress((void**)&vth, g_vth);

    cudaFuncSetAttribute(gemm_qkv, cudaFuncAttributeMaxDynamicSharedMemorySize, GEMM_SMEM);
    cudaFuncSetAttribute(gemm_wo,  cudaFuncAttributeMaxDynamicSharedMemorySize, GEMM_SMEM);
    cudaFuncSetAttribute(attn_mma, cudaFuncAttributeMaxDynamicSharedMemorySize, ATTN_SMEM);

    tohalf5_kernel<<<(NXF4 + 4*NWF4)/256, 256>>>(x, wq, wk, wv, wo, x16, w16);

    gemm_qkv<<<dim3(48, 32), 256, GEMM_SMEM>>>(x16, w16, qh, ql, kh, v16);

    vsplit_kernel<<<dim3(DKH/32, SEQ/32, BH), 256>>>();

    attn_mma<<<dim3(SEQ/128, BH), 256, ATTN_SMEM>>>(qh, ql, kh, vth, c16);

    gemm_wo<<<dim3(16, 32), 256, GEMM_SMEM>>>(c16, w16 + 3*(size_t)DM*DM, bo, out);
}